// round 1
// baseline (speedup 1.0000x reference)
#include <cuda_runtime.h>

// Problem constants
#define NN 116          // nodes per graph (= C_IN)
#define CC 116          // input channels
#define HH 128          // hidden dim
#define SA_STR 124      // A_norm row stride (pad): banks (28*i+k)%32 distinct for 8 rows
#define SX_STR 132      // [128][132] buffer stride: rotates banks per k
#define NTHREADS 512
#define NTILES (29*16)  // 29 row-tiles (4 rows) x 16 col-tiles (4+4 cols split at +64)

static constexpr int SMEM_FLOATS = NN*SA_STR + 2*HH*SX_STR + 128;
static constexpr size_t SMEM_BYTES = (size_t)SMEM_FLOATS * sizeof(float);

#define FMA8(r, av)                                         \
    acc[r][0] += (av)*bl.x; acc[r][1] += (av)*bl.y;         \
    acc[r][2] += (av)*bl.z; acc[r][3] += (av)*bl.w;         \
    acc[r][4] += (av)*bh.x; acc[r][5] += (av)*bh.y;         \
    acc[r][6] += (av)*bh.z; acc[r][7] += (av)*bh.w;

__global__ __launch_bounds__(NTHREADS, 1)
void gcn_kernel(const float* __restrict__ ga,
                const float* __restrict__ gf,
                const float* __restrict__ gW1,
                const float* __restrict__ gb1,
                const float* __restrict__ gW2,
                const float* __restrict__ gb2,
                float* __restrict__ gout)
{
    extern __shared__ float smem[];
    float* sA = smem;                    // [116][124]  A_norm
    float* sX = sA + NN*SA_STR;          // [128][132]  W1 -> h
    float* sY = sX + HH*SX_STR;          // [128][132]  g  -> t
    float* sd = sY + HH*SX_STR;          // [116]       deg^-1/2

    const int b   = blockIdx.x;
    const int tid = threadIdx.x;
    const float* ab = ga + (size_t)b * NN * NN;
    const float* fb = gf + (size_t)b * NN * CC;
    float*       ob = gout + (size_t)b * NN * HH;

    // ---- load |a| into sA, W1 into sX ----
    for (int idx = tid; idx < NN*NN; idx += NTHREADS) {
        int i = idx / NN, j = idx - i * NN;
        sA[i*SA_STR + j] = fabsf(__ldg(ab + idx));
    }
    for (int idx = tid; idx < CC*HH; idx += NTHREADS) {
        int k = idx >> 7, j = idx & 127;
        sX[k*SX_STR + j] = __ldg(gW1 + idx);
    }
    __syncthreads();

    // ---- row sums -> d = rsqrt(sum(|a|) + 1) ----
    {
        int warp = tid >> 5, lane = tid & 31;
        for (int i = warp; i < NN; i += NTHREADS/32) {
            float s = 0.f;
            for (int j = lane; j < NN; j += 32) s += sA[i*SA_STR + j];
            #pragma unroll
            for (int off = 16; off; off >>= 1)
                s += __shfl_xor_sync(0xffffffffu, s, off);
            if (lane == 0) sd[i] = rsqrtf(s + 1.0f);
        }
    }
    __syncthreads();

    // ---- A_norm = d_i * (|a| + I) * d_j in place ----
    for (int idx = tid; idx < NN*NN; idx += NTHREADS) {
        int i = idx / NN, j = idx - i * NN;
        float v = sA[i*SA_STR + j] + (i == j ? 1.0f : 0.0f);
        sA[i*SA_STR + j] = sd[i] * sd[j] * v;
    }
    __syncthreads();

    const bool active = (tid < NTILES);
    const int it = tid >> 4;       // 0..28
    const int jt = tid & 15;       // 0..15
    const int i0 = it * 4;
    const int j0 = jt * 4;         // columns {j0..j0+3} and {j0+64..j0+67}

    // ================= step 3: sY = f(gmem) @ W1(sX) =================
    if (active) {
        float acc[4][8];
        #pragma unroll
        for (int r = 0; r < 4; r++)
            #pragma unroll
            for (int c = 0; c < 8; c++) acc[r][c] = 0.f;

        for (int k = 0; k < CC; k += 4) {
            float fa[4][4];
            #pragma unroll
            for (int r = 0; r < 4; r++)
                *reinterpret_cast<float4*>(fa[r]) =
                    __ldg(reinterpret_cast<const float4*>(fb + (i0 + r)*CC + k));
            #pragma unroll
            for (int s = 0; s < 4; s++) {
                const float* bp = sX + (k + s)*SX_STR + j0;
                float4 bl = *reinterpret_cast<const float4*>(bp);
                float4 bh = *reinterpret_cast<const float4*>(bp + 64);
                FMA8(0, fa[0][s]); FMA8(1, fa[1][s]);
                FMA8(2, fa[2][s]); FMA8(3, fa[3][s]);
            }
        }
        #pragma unroll
        for (int r = 0; r < 4; r++) {
            float* yp = sY + (i0 + r)*SX_STR + j0;
            *reinterpret_cast<float4*>(yp)      = make_float4(acc[r][0], acc[r][1], acc[r][2], acc[r][3]);
            *reinterpret_cast<float4*>(yp + 64) = make_float4(acc[r][4], acc[r][5], acc[r][6], acc[r][7]);
        }
    }
    __syncthreads();

    // ================= step 4: sX = relu(A_norm @ sY + b1) =================
    if (active) {
        float4 b1l = __ldg(reinterpret_cast<const float4*>(gb1 + j0));
        float4 b1h = __ldg(reinterpret_cast<const float4*>(gb1 + j0 + 64));
        float acc[4][8];
        #pragma unroll
        for (int r = 0; r < 4; r++)
            #pragma unroll
            for (int c = 0; c < 8; c++) acc[r][c] = 0.f;

        #pragma unroll 4
        for (int k = 0; k < NN; k++) {
            const float* bp = sY + k*SX_STR + j0;
            float4 bl = *reinterpret_cast<const float4*>(bp);
            float4 bh = *reinterpret_cast<const float4*>(bp + 64);
            float a0 = sA[(i0 + 0)*SA_STR + k];
            float a1 = sA[(i0 + 1)*SA_STR + k];
            float a2 = sA[(i0 + 2)*SA_STR + k];
            float a3 = sA[(i0 + 3)*SA_STR + k];
            FMA8(0, a0); FMA8(1, a1); FMA8(2, a2); FMA8(3, a3);
        }
        #pragma unroll
        for (int r = 0; r < 4; r++) {
            float* xp = sX + (i0 + r)*SX_STR + j0;
            *reinterpret_cast<float4*>(xp) = make_float4(
                fmaxf(acc[r][0] + b1l.x, 0.f), fmaxf(acc[r][1] + b1l.y, 0.f),
                fmaxf(acc[r][2] + b1l.z, 0.f), fmaxf(acc[r][3] + b1l.w, 0.f));
            *reinterpret_cast<float4*>(xp + 64) = make_float4(
                fmaxf(acc[r][4] + b1h.x, 0.f), fmaxf(acc[r][5] + b1h.y, 0.f),
                fmaxf(acc[r][6] + b1h.z, 0.f), fmaxf(acc[r][7] + b1h.w, 0.f));
        }
    }
    __syncthreads();

    // ================= step 5: sY = h(sX) @ W2(gmem) =================
    if (active) {
        float acc[4][8];
        #pragma unroll
        for (int r = 0; r < 4; r++)
            #pragma unroll
            for (int c = 0; c < 8; c++) acc[r][c] = 0.f;

        #pragma unroll 2
        for (int k = 0; k < HH; k++) {
            float4 bl = __ldg(reinterpret_cast<const float4*>(gW2 + k*HH + j0));
            float4 bh = __ldg(reinterpret_cast<const float4*>(gW2 + k*HH + j0 + 64));
            float a0 = sX[(i0 + 0)*SX_STR + k];
            float a1 = sX[(i0 + 1)*SX_STR + k];
            float a2 = sX[(i0 + 2)*SX_STR + k];
            float a3 = sX[(i0 + 3)*SX_STR + k];
            FMA8(0, a0); FMA8(1, a1); FMA8(2, a2); FMA8(3, a3);
        }
        #pragma unroll
        for (int r = 0; r < 4; r++) {
            float* yp = sY + (i0 + r)*SX_STR + j0;
            *reinterpret_cast<float4*>(yp)      = make_float4(acc[r][0], acc[r][1], acc[r][2], acc[r][3]);
            *reinterpret_cast<float4*>(yp + 64) = make_float4(acc[r][4], acc[r][5], acc[r][6], acc[r][7]);
        }
    }
    __syncthreads();

    // ================= step 6: out = relu(A_norm @ sY + b2) =================
    if (active) {
        float4 b2l = __ldg(reinterpret_cast<const float4*>(gb2 + j0));
        float4 b2h = __ldg(reinterpret_cast<const float4*>(gb2 + j0 + 64));
        float acc[4][8];
        #pragma unroll
        for (int r = 0; r < 4; r++)
            #pragma unroll
            for (int c = 0; c < 8; c++) acc[r][c] = 0.f;

        #pragma unroll 4
        for (int k = 0; k < NN; k++) {
            const float* bp = sY + k*SX_STR + j0;
            float4 bl = *reinterpret_cast<const float4*>(bp);
            float4 bh = *reinterpret_cast<const float4*>(bp + 64);
            float a0 = sA[(i0 + 0)*SA_STR + k];
            float a1 = sA[(i0 + 1)*SA_STR + k];
            float a2 = sA[(i0 + 2)*SA_STR + k];
            float a3 = sA[(i0 + 3)*SA_STR + k];
            FMA8(0, a0); FMA8(1, a1); FMA8(2, a2); FMA8(3, a3);
        }
        #pragma unroll
        for (int r = 0; r < 4; r++) {
            float* op = ob + (i0 + r)*HH + j0;
            float4 o0 = make_float4(
                fmaxf(acc[r][0] + b2l.x, 0.f), fmaxf(acc[r][1] + b2l.y, 0.f),
                fmaxf(acc[r][2] + b2l.z, 0.f), fmaxf(acc[r][3] + b2l.w, 0.f));
            float4 o1 = make_float4(
                fmaxf(acc[r][4] + b2h.x, 0.f), fmaxf(acc[r][5] + b2h.y, 0.f),
                fmaxf(acc[r][6] + b2h.z, 0.f), fmaxf(acc[r][7] + b2h.w, 0.f));
            *reinterpret_cast<float4*>(op)      = o0;
            *reinterpret_cast<float4*>(op + 64) = o1;
        }
    }
}

extern "C" void kernel_launch(void* const* d_in, const int* in_sizes, int n_in,
                              void* d_out, int out_size)
{
    const float* a  = (const float*)d_in[0];
    const float* f  = (const float*)d_in[1];
    const float* W1 = (const float*)d_in[2];
    const float* b1 = (const float*)d_in[3];
    const float* W2 = (const float*)d_in[4];
    const float* b2 = (const float*)d_in[5];
    float* out = (float*)d_out;

    int batch = in_sizes[0] / (NN * NN);

    // Idempotent attribute set (immediate host-side op; not a stream op, capture-safe)
    cudaFuncSetAttribute(gcn_kernel, cudaFuncAttributeMaxDynamicSharedMemorySize,
                         (int)SMEM_BYTES);

    gcn_kernel<<<batch, NTHREADS, SMEM_BYTES>>>(a, f, W1, b1, W2, b2, out);
}

// round 3
// speedup vs baseline: 2.1635x; 2.1635x over previous
#include <cuda_runtime.h>
#include <cstdint>

#define NN 116
#define HH 128
#define NTHREADS 256
#define STR_A 132     // A-operand row stride (floats): banks (4r+c)%32 all-distinct
#define STR_B 136     // B-operand row stride (floats): banks (8c+r)%32 all-distinct

static constexpr size_t SMEM_BYTES = (size_t)(2 * 128 * STR_A + 128 * STR_B) * 4;

__device__ __forceinline__ float to_tf32(float x) {
    uint32_t u;
    asm("cvt.rna.tf32.f32 %0, %1;" : "=r"(u) : "f"(x));
    return __uint_as_float(u);
}

#define MMA_TF32(d, a, b)                                                     \
    asm volatile(                                                             \
        "mma.sync.aligned.m16n8k8.row.col.f32.tf32.tf32.f32 "                 \
        "{%0,%1,%2,%3}, {%4,%5,%6,%7}, {%8,%9}, {%0,%1,%2,%3};"               \
        : "+f"(d[0]), "+f"(d[1]), "+f"(d[2]), "+f"(d[3])                      \
        : "r"(a[0]), "r"(a[1]), "r"(a[2]), "r"(a[3]), "r"(b[0]), "r"(b[1]))

// One full 128x128x128 GEMM: D(frags) = A(sApd, row-major, STR_A) * B(sBpd, [k][n], STR_B)
// Warp wid: rows [wm*64, wm*64+64), cols [wn*32, wn*32+32).
__device__ __forceinline__ void gemm128(const float* __restrict__ Aop,
                                        const float* __restrict__ Bop,
                                        float acc[4][4][4],
                                        int wm, int wn, int lane)
{
    const int r = lane >> 2, c = lane & 3;
    #pragma unroll
    for (int mi = 0; mi < 4; mi++)
        #pragma unroll
        for (int ni = 0; ni < 4; ni++)
            #pragma unroll
            for (int q = 0; q < 4; q++) acc[mi][ni][q] = 0.f;

    #pragma unroll 1
    for (int ks = 0; ks < 16; ks++) {
        const int k0 = ks * 8;
        uint32_t fa[4][4], fb[4][2];
        #pragma unroll
        for (int mi = 0; mi < 4; mi++) {
            const float* ap = Aop + (wm * 64 + mi * 16 + r) * STR_A + k0 + c;
            fa[mi][0] = __float_as_uint(ap[0]);
            fa[mi][1] = __float_as_uint(ap[8 * STR_A]);
            fa[mi][2] = __float_as_uint(ap[4]);
            fa[mi][3] = __float_as_uint(ap[8 * STR_A + 4]);
        }
        #pragma unroll
        for (int ni = 0; ni < 4; ni++) {
            const float* bp = Bop + (k0 + c) * STR_B + wn * 32 + ni * 8 + r;
            fb[ni][0] = __float_as_uint(bp[0]);
            fb[ni][1] = __float_as_uint(bp[4 * STR_B]);
        }
        #pragma unroll
        for (int mi = 0; mi < 4; mi++)
            #pragma unroll
            for (int ni = 0; ni < 4; ni++)
                MMA_TF32(acc[mi][ni], fa[mi], fb[ni]);
    }
}

__global__ __launch_bounds__(NTHREADS, 1)
void gcn_mma(const float* __restrict__ ga, const float* __restrict__ gf,
             const float* __restrict__ gW1, const float* __restrict__ gb1,
             const float* __restrict__ gW2, const float* __restrict__ gb2,
             float* __restrict__ gout)
{
    extern __shared__ float sm[];
    float* sA = sm;                          // A_norm   [128][STR_A]
    float* sX = sm + 128 * STR_A;            // f -> h   [128][STR_A]
    float* sB = sm + 2 * 128 * STR_A;        // W1/g/W2/t [128][STR_B]
    __shared__ float sd[128], sb1[128], sb2[128];

    const int tid = threadIdx.x;
    const int wid = tid >> 5, lane = tid & 31;
    const int wm = wid & 1, wn = wid >> 1;   // 2x4 warp grid -> 64x32 tiles
    const int b = blockIdx.x;
    const float* ab = ga + (size_t)b * NN * NN;
    const float* fb = gf + (size_t)b * NN * NN;
    float*       ob = gout + (size_t)b * NN * HH;

    // ---- zero pads (full buffers) ----
    for (int i = tid; i < 2 * 128 * STR_A + 128 * STR_B; i += NTHREADS) sm[i] = 0.f;
    if (tid < 128) { sb1[tid] = __ldg(gb1 + tid); sb2[tid] = __ldg(gb2 + tid); }
    __syncthreads();

    // ---- fill |a|, f(tf32), W1(tf32) ----
    for (int idx = tid; idx < NN * NN; idx += NTHREADS) {
        int i = idx / NN, j = idx - i * NN;
        sA[i * STR_A + j] = fabsf(__ldg(ab + idx));
        sX[i * STR_A + j] = to_tf32(__ldg(fb + idx));
    }
    for (int idx = tid; idx < NN * HH; idx += NTHREADS) {
        int k = idx >> 7, n = idx & 127;
        sB[k * STR_B + n] = to_tf32(__ldg(gW1 + idx));
    }
    __syncthreads();

    // ---- d = rsqrt(rowsum(|a|) + 1) ----
    for (int i = wid; i < NN; i += 8) {
        float s = sA[i * STR_A + lane] + sA[i * STR_A + lane + 32]
                + sA[i * STR_A + lane + 64] + sA[i * STR_A + lane + 96];
        #pragma unroll
        for (int o = 16; o; o >>= 1) s += __shfl_xor_sync(0xffffffffu, s, o);
        if (!lane) sd[i] = rsqrtf(s + 1.0f);
    }
    __syncthreads();

    // ---- A_norm = tf32(d_i d_j (|a| + I)) in place ----
    for (int idx = tid; idx < NN * NN; idx += NTHREADS) {
        int i = idx / NN, j = idx - i * NN;
        float v = sA[i * STR_A + j] + (i == j ? 1.0f : 0.0f);
        sA[i * STR_A + j] = to_tf32(sd[i] * sd[j] * v);
    }
    __syncthreads();

    const int r = lane >> 2, c2 = (lane & 3) * 2;
    float acc[4][4][4];

    // ===== G1: g = f @ W1 =====
    gemm128(sX, sB, acc, wm, wn, lane);
    __syncthreads();                          // all warps done reading W1
    #pragma unroll
    for (int mi = 0; mi < 4; mi++)
        #pragma unroll
        for (int ni = 0; ni < 4; ni++) {
            int row = wm * 64 + mi * 16 + r, col = wn * 32 + ni * 8 + c2;
            sB[row * STR_B + col]           = to_tf32(acc[mi][ni][0]);
            sB[row * STR_B + col + 1]       = to_tf32(acc[mi][ni][1]);
            sB[(row + 8) * STR_B + col]     = to_tf32(acc[mi][ni][2]);
            sB[(row + 8) * STR_B + col + 1] = to_tf32(acc[mi][ni][3]);
        }
    __syncthreads();

    // ===== G2: h = relu(A_norm @ g + b1) =====
    gemm128(sA, sB, acc, wm, wn, lane);
    __syncthreads();                          // all warps done reading g
    #pragma unroll
    for (int mi = 0; mi < 4; mi++)
        #pragma unroll
        for (int ni = 0; ni < 4; ni++) {
            int row = wm * 64 + mi * 16 + r, col = wn * 32 + ni * 8 + c2;
            sX[row * STR_A + col]           = to_tf32(fmaxf(acc[mi][ni][0] + sb1[col], 0.f));
            sX[row * STR_A + col + 1]       = to_tf32(fmaxf(acc[mi][ni][1] + sb1[col + 1], 0.f));
            sX[(row + 8) * STR_A + col]     = to_tf32(fmaxf(acc[mi][ni][2] + sb1[col], 0.f));
            sX[(row + 8) * STR_A + col + 1] = to_tf32(fmaxf(acc[mi][ni][3] + sb1[col + 1], 0.f));
        }
    for (int idx = tid; idx < HH * HH; idx += NTHREADS) {
        int k = idx >> 7, n = idx & 127;
        sB[k * STR_B + n] = to_tf32(__ldg(gW2 + idx));
    }
    __syncthreads();

    // ===== G3: t = h @ W2 =====
    gemm128(sX, sB, acc, wm, wn, lane);
    __syncthreads();                          // all warps done reading W2
    #pragma unroll
    for (int mi = 0; mi < 4; mi++)
        #pragma unroll
        for (int ni = 0; ni < 4; ni++) {
            int row = wm * 64 + mi * 16 + r, col = wn * 32 + ni * 8 + c2;
            sB[row * STR_B + col]           = to_tf32(acc[mi][ni][0]);
            sB[row * STR_B + col + 1]       = to_tf32(acc[mi][ni][1]);
            sB[(row + 8) * STR_B + col]     = to_tf32(acc[mi][ni][2]);
            sB[(row + 8) * STR_B + col + 1] = to_tf32(acc[mi][ni][3]);
        }
    __syncthreads();

    // ===== G4: out = relu(A_norm @ t + b2) =====
    gemm128(sA, sB, acc, wm, wn, lane);
    #pragma unroll
    for (int mi = 0; mi < 4; mi++)
        #pragma unroll
        for (int ni = 0; ni < 4; ni++) {
            int row = wm * 64 + mi * 16 + r, col = wn * 32 + ni * 8 + c2;
            if (row < NN) {
                float2 v0 = make_float2(fmaxf(acc[mi][ni][0] + sb2[col], 0.f),
                                        fmaxf(acc[mi][ni][1] + sb2[col + 1], 0.f));
                *reinterpret_cast<float2*>(ob + (size_t)row * HH + col) = v0;
            }
            if (row + 8 < NN) {
                float2 v1 = make_float2(fmaxf(acc[mi][ni][2] + sb2[col], 0.f),
                                        fmaxf(acc[mi][ni][3] + sb2[col + 1], 0.f));
                *reinterpret_cast<float2*>(ob + (size_t)(row + 8) * HH + col) = v1;
            }
        }
}

extern "C" void kernel_launch(void* const* d_in, const int* in_sizes, int n_in,
                              void* d_out, int out_size)
{
    const float* a  = (const float*)d_in[0];
    const float* f  = (const float*)d_in[1];
    const float* W1 = (const float*)d_in[2];
    const float* b1 = (const float*)d_in[3];
    const float* W2 = (const float*)d_in[4];
    const float* b2 = (const float*)d_in[5];
    float* out = (float*)d_out;

    int batch = in_sizes[0] / (NN * NN);

    cudaFuncSetAttribute(gcn_mma, cudaFuncAttributeMaxDynamicSharedMemorySize, (int)SMEM_BYTES);
    gcn_mma<<<batch, NTHREADS, SMEM_BYTES>>>(a, f, W1, b1, W2, b2, out);
}

// round 4
// speedup vs baseline: 2.7388x; 1.2659x over previous
#include <cuda_runtime.h>
#include <cstdint>

#define NN 116
#define HH 128
#define NTHREADS 512
#define STR_A 132     // A-operand row stride (floats): banks (4r+c)%32 all-distinct
#define STR_B 136     // B-operand row stride (floats): banks (8c+r)%32 all-distinct

static constexpr size_t SMEM_BYTES = (size_t)(2 * 128 * STR_A + 128 * STR_B) * 4;

__device__ __forceinline__ float to_tf32(float x) {
    uint32_t u;
    asm("cvt.rna.tf32.f32 %0, %1;" : "=r"(u) : "f"(x));
    return __uint_as_float(u);
}

#define MMA_TF32(d, a, b)                                                     \
    asm volatile(                                                             \
        "mma.sync.aligned.m16n8k8.row.col.f32.tf32.tf32.f32 "                 \
        "{%0,%1,%2,%3}, {%4,%5,%6,%7}, {%8,%9}, {%0,%1,%2,%3};"               \
        : "+f"(d[0]), "+f"(d[1]), "+f"(d[2]), "+f"(d[3])                      \
        : "r"(a[0]), "r"(a[1]), "r"(a[2]), "r"(a[3]), "r"(b[0]), "r"(b[1]))

// 128x128x128 GEMM, 16 warps in a 4x4 grid; warp tile 32(m) x 32(n).
__device__ __forceinline__ void gemm128(const float* __restrict__ Aop,
                                        const float* __restrict__ Bop,
                                        float acc[2][4][4],
                                        int wm, int wn, int lane)
{
    const int r = lane >> 2, c = lane & 3;
    #pragma unroll
    for (int mi = 0; mi < 2; mi++)
        #pragma unroll
        for (int ni = 0; ni < 4; ni++)
            #pragma unroll
            for (int q = 0; q < 4; q++) acc[mi][ni][q] = 0.f;

    const float* apb = Aop + (wm * 32 + r) * STR_A + c;
    const float* bpb = Bop + c * STR_B + wn * 32 + r;

    #pragma unroll 2
    for (int ks = 0; ks < 16; ks++) {
        const int k0 = ks * 8;
        uint32_t fa[2][4], fb[4][2];
        #pragma unroll
        for (int mi = 0; mi < 2; mi++) {
            const float* ap = apb + mi * 16 * STR_A + k0;
            fa[mi][0] = __float_as_uint(ap[0]);
            fa[mi][1] = __float_as_uint(ap[8 * STR_A]);
            fa[mi][2] = __float_as_uint(ap[4]);
            fa[mi][3] = __float_as_uint(ap[8 * STR_A + 4]);
        }
        #pragma unroll
        for (int ni = 0; ni < 4; ni++) {
            const float* bp = bpb + k0 * STR_B + ni * 8;
            fb[ni][0] = __float_as_uint(bp[0]);
            fb[ni][1] = __float_as_uint(bp[4 * STR_B]);
        }
        #pragma unroll
        for (int mi = 0; mi < 2; mi++)
            #pragma unroll
            for (int ni = 0; ni < 4; ni++)
                MMA_TF32(acc[mi][ni], fa[mi], fb[ni]);
    }
}

__global__ __launch_bounds__(NTHREADS, 1)
void gcn_mma(const float* __restrict__ ga, const float* __restrict__ gf,
             const float* __restrict__ gW1, const float* __restrict__ gb1,
             const float* __restrict__ gW2, const float* __restrict__ gb2,
             float* __restrict__ gout)
{
    extern __shared__ float sm[];
    float* sA = sm;                          // A_norm    [128][STR_A]
    float* sX = sm + 128 * STR_A;            // f -> h    [128][STR_A]
    float* sB = sm + 2 * 128 * STR_A;        // W1/g/W2/t [128][STR_B]
    __shared__ float sd[128], sb1[128], sb2[128];

    const int tid = threadIdx.x;
    const int wid = tid >> 5, lane = tid & 31;
    const int wm = wid & 3, wn = wid >> 2;   // 4x4 warp grid -> 32x32 tiles
    const int b = blockIdx.x;
    const float* ab = ga + (size_t)b * NN * NN;
    const float* fb = gf + (size_t)b * NN * NN;
    float*       ob = gout + (size_t)b * NN * HH;

    // ---- zero pads (full buffers) ----
    for (int i = tid; i < 2 * 128 * STR_A + 128 * STR_B; i += NTHREADS) sm[i] = 0.f;
    if (tid < 128) { sb1[tid] = __ldg(gb1 + tid); sb2[tid] = __ldg(gb2 + tid); }
    __syncthreads();

    // ---- fill |a|, f(tf32), W1(tf32) ----
    for (int idx = tid; idx < NN * NN; idx += NTHREADS) {
        int i = idx / NN, j = idx - i * NN;
        sA[i * STR_A + j] = fabsf(__ldg(ab + idx));
        sX[i * STR_A + j] = to_tf32(__ldg(fb + idx));
    }
    for (int idx = tid; idx < NN * HH; idx += NTHREADS) {
        int k = idx >> 7, n = idx & 127;
        sB[k * STR_B + n] = to_tf32(__ldg(gW1 + idx));
    }
    __syncthreads();

    // ---- d = rsqrt(rowsum(|a|) + 1) ----
    for (int i = wid; i < NN; i += 16) {
        float s = sA[i * STR_A + lane] + sA[i * STR_A + lane + 32]
                + sA[i * STR_A + lane + 64] + sA[i * STR_A + lane + 96];
        #pragma unroll
        for (int o = 16; o; o >>= 1) s += __shfl_xor_sync(0xffffffffu, s, o);
        if (!lane) sd[i] = rsqrtf(s + 1.0f);
    }
    __syncthreads();

    // ---- A_norm = tf32(d_i d_j (|a| + I)) in place ----
    for (int idx = tid; idx < NN * NN; idx += NTHREADS) {
        int i = idx / NN, j = idx - i * NN;
        float v = sA[i * STR_A + j] + (i == j ? 1.0f : 0.0f);
        sA[i * STR_A + j] = to_tf32(sd[i] * sd[j] * v);
    }
    __syncthreads();

    const int r = lane >> 2, c2 = (lane & 3) * 2;
    float acc[2][4][4];

    // ===== G1: g = f @ W1 =====
    gemm128(sX, sB, acc, wm, wn, lane);
    __syncthreads();                          // all warps done reading W1
    #pragma unroll
    for (int mi = 0; mi < 2; mi++)
        #pragma unroll
        for (int ni = 0; ni < 4; ni++) {
            int row = wm * 32 + mi * 16 + r, col = wn * 32 + ni * 8 + c2;
            sB[row * STR_B + col]           = to_tf32(acc[mi][ni][0]);
            sB[row * STR_B + col + 1]       = to_tf32(acc[mi][ni][1]);
            sB[(row + 8) * STR_B + col]     = to_tf32(acc[mi][ni][2]);
            sB[(row + 8) * STR_B + col + 1] = to_tf32(acc[mi][ni][3]);
        }
    __syncthreads();

    // ===== G2: h = relu(A_norm @ g + b1) =====
    gemm128(sA, sB, acc, wm, wn, lane);
    __syncthreads();                          // all warps done reading g
    #pragma unroll
    for (int mi = 0; mi < 2; mi++)
        #pragma unroll
        for (int ni = 0; ni < 4; ni++) {
            int row = wm * 32 + mi * 16 + r, col = wn * 32 + ni * 8 + c2;
            sX[row * STR_A + col]           = to_tf32(fmaxf(acc[mi][ni][0] + sb1[col], 0.f));
            sX[row * STR_A + col + 1]       = to_tf32(fmaxf(acc[mi][ni][1] + sb1[col + 1], 0.f));
            sX[(row + 8) * STR_A + col]     = to_tf32(fmaxf(acc[mi][ni][2] + sb1[col], 0.f));
            sX[(row + 8) * STR_A + col + 1] = to_tf32(fmaxf(acc[mi][ni][3] + sb1[col + 1], 0.f));
        }
    for (int idx = tid; idx < HH * HH; idx += NTHREADS) {
        int k = idx >> 7, n = idx & 127;
        sB[k * STR_B + n] = to_tf32(__ldg(gW2 + idx));
    }
    __syncthreads();

    // ===== G3: t = h @ W2 =====
    gemm128(sX, sB, acc, wm, wn, lane);
    __syncthreads();                          // all warps done reading W2
    #pragma unroll
    for (int mi = 0; mi < 2; mi++)
        #pragma unroll
        for (int ni = 0; ni < 4; ni++) {
            int row = wm * 32 + mi * 16 + r, col = wn * 32 + ni * 8 + c2;
            sB[row * STR_B + col]           = to_tf32(acc[mi][ni][0]);
            sB[row * STR_B + col + 1]       = to_tf32(acc[mi][ni][1]);
            sB[(row + 8) * STR_B + col]     = to_tf32(acc[mi][ni][2]);
            sB[(row + 8) * STR_B + col + 1] = to_tf32(acc[mi][ni][3]);
        }
    __syncthreads();

    // ===== G4: out = relu(A_norm @ t + b2) =====
    gemm128(sA, sB, acc, wm, wn, lane);
    #pragma unroll
    for (int mi = 0; mi < 2; mi++)
        #pragma unroll
        for (int ni = 0; ni < 4; ni++) {
            int row = wm * 32 + mi * 16 + r, col = wn * 32 + ni * 8 + c2;
            if (row < NN) {
                float2 v0 = make_float2(fmaxf(acc[mi][ni][0] + sb2[col], 0.f),
                                        fmaxf(acc[mi][ni][1] + sb2[col + 1], 0.f));
                *reinterpret_cast<float2*>(ob + (size_t)row * HH + col) = v0;
            }
            if (row + 8 < NN) {
                float2 v1 = make_float2(fmaxf(acc[mi][ni][2] + sb2[col], 0.f),
                                        fmaxf(acc[mi][ni][3] + sb2[col + 1], 0.f));
                *reinterpret_cast<float2*>(ob + (size_t)(row + 8) * HH + col) = v1;
            }
        }
}

extern "C" void kernel_launch(void* const* d_in, const int* in_sizes, int n_in,
                              void* d_out, int out_size)
{
    const float* a  = (const float*)d_in[0];
    const float* f  = (const float*)d_in[1];
    const float* W1 = (const float*)d_in[2];
    const float* b1 = (const float*)d_in[3];
    const float* W2 = (const float*)d_in[4];
    const float* b2 = (const float*)d_in[5];
    float* out = (float*)d_out;

    int batch = in_sizes[0] / (NN * NN);

    cudaFuncSetAttribute(gcn_mma, cudaFuncAttributeMaxDynamicSharedMemorySize, (int)SMEM_BYTES);
    gcn_mma<<<batch, NTHREADS, SMEM_BYTES>>>(a, f, W1, b1, W2, b2, out);
}